// round 8
// baseline (speedup 1.0000x reference)
#include <cuda_runtime.h>
#include <math_constants.h>

// ---------------- problem constants (fixed shapes) ----------------
#define N_NODES  8192
#define N_EDGES  262144
#define IN_C     64
#define DIN      192          // IN_C * K
#define DOUT     192          // OUT_C * K
#define G_GRAPHS 64
#define D3       576          // 3 * DOUT
#define H1DIM    384
#define H2DIM    192
#define NCLS     10
#define BN_EPS   1e-5f

// ---------------- device scratch ----------------
__device__ float g_deg[N_NODES];        // zeroed by funnel tail
__device__ int   g_rowCnt[N_NODES];     // zeroed by funnel tail
__device__ float g_dinv[N_NODES];
__device__ int   g_rowPtr[N_NODES + 1];
__device__ int   g_colIdx[N_EDGES];
__device__ float g_val[N_EDGES];
__device__ float g_Hcat[N_NODES * DIN]; // [x | Lx | L^2 x]
__device__ float g_sigma;
__device__ float g_sum[DOUT], g_sumsq[DOUT];        // BN1 raw stats (init in k_build)
__device__ float g_gsum[G_GRAPHS * DOUT];           // per-graph raw col sums
__device__ int   g_gmaxi[G_GRAPHS * DOUT];          // ordered-int max
__device__ int   g_gmini[G_GRAPHS * DOUT];          // ordered-int min

__device__ __forceinline__ int f2o(float f) {
    int i = __float_as_int(f);
    return i >= 0 ? i : i ^ 0x7FFFFFFF;
}
__device__ __forceinline__ float o2f(int i) {
    return __int_as_float(i >= 0 ? i : i ^ 0x7FFFFFFF);
}

// ---------------- kernels ----------------

__global__ void k_degree(const int* __restrict__ ei) {
    int e = blockIdx.x * blockDim.x + threadIdx.x;
    if (e < N_EDGES) atomicAdd(&g_deg[ei[e]], 1.0f);
}

// dinv + exclusive scan (warp-shuffle) + spectral sigma, one block of 1024
__global__ void k_scan(const float* __restrict__ W, const float* __restrict__ u) {
    __shared__ int   wsum[32];
    __shared__ float fred[256];
    int t = threadIdx.x, lane = t & 31, wid = t >> 5;
    int base = t * 8;
    int loc[8]; int s = 0;
#pragma unroll
    for (int j = 0; j < 8; ++j) {
        float d = g_deg[base + j];
        g_dinv[base + j] = (d > 0.f) ? rsqrtf(fmaxf(d, 1.f)) : 0.f;
        loc[j] = s; s += (int)d;
    }
    int isc = s;
#pragma unroll
    for (int off = 1; off < 32; off <<= 1) {
        int v = __shfl_up_sync(0xffffffff, isc, off);
        if (lane >= off) isc += v;
    }
    if (lane == 31) wsum[wid] = isc;
    __syncthreads();
    if (wid == 0) {
        int v = wsum[lane];
        int sc = v;
#pragma unroll
        for (int off = 1; off < 32; off <<= 1) {
            int q = __shfl_up_sync(0xffffffff, sc, off);
            if (lane >= off) sc += q;
        }
        wsum[lane] = sc - v;
    }
    __syncthreads();
    int tbase = wsum[wid] + (isc - s);
#pragma unroll
    for (int j = 0; j < 8; ++j) g_rowPtr[base + j] = tbase + loc[j];
    if (t == 1023) g_rowPtr[N_NODES] = tbase + s;

    float vsq = 0.f;
    if (t < DIN) {
        float v = 0.f;
        for (int i = 0; i < DOUT; ++i) v = fmaf(W[i * DIN + t], u[i], v);
        vsq = v * v;
    }
    if (t < 256) fred[t] = vsq;
    __syncthreads();
    for (int off = 128; off; off >>= 1) {
        if (t < 256 && t < off) fred[t] += fred[t + off];
        __syncthreads();
    }
    if (t == 0) {
        float ns = fred[0];
        g_sigma = ns / (sqrtf(ns) + 1e-12f);
    }
}

// CSR fill + init of stat arrays consumed by gemm/funnel later this replay
__global__ void k_build(const int* __restrict__ ei) {
    int e = blockIdx.x * blockDim.x + threadIdx.x;
    if (e < G_GRAPHS * DOUT) {
        g_gsum[e]  = 0.f;
        g_gmaxi[e] = 0x80000000;   // INT_MIN  (< any ordered float)
        g_gmini[e] = 0x7FFFFFFF;   // INT_MAX
    }
    if (e < DOUT) { g_sum[e] = 0.f; g_sumsq[e] = 0.f; }
    if (e >= N_EDGES) return;
    int r = ei[e];
    int c = ei[N_EDGES + e];
    int pos = g_rowPtr[r] + atomicAdd(&g_rowCnt[r], 1);
    g_colIdx[pos] = c;
    g_val[pos] = -g_dinv[r] * g_dinv[c];
}

// hop 1: Hcat[:,0:64]=x, Hcat[:,64:128]=x+L_off@x   (warp/row, 4-edge unroll)
__global__ void k_spmm1(const float* __restrict__ x) {
    int w = (blockIdx.x * blockDim.x + threadIdx.x) >> 5;
    int lane = threadIdx.x & 31;
    if (w >= N_NODES) return;
    float2 xv0 = *(const float2*)&x[w * 64 + 2 * lane];
    float2 acc = xv0;
    int s = g_rowPtr[w], e = g_rowPtr[w + 1];
    int p = s;
    for (; p + 3 < e; p += 4) {
        int   c0 = __ldg(&g_colIdx[p]),     c1 = __ldg(&g_colIdx[p + 1]);
        int   c2 = __ldg(&g_colIdx[p + 2]), c3 = __ldg(&g_colIdx[p + 3]);
        float v0 = __ldg(&g_val[p]),        v1 = __ldg(&g_val[p + 1]);
        float v2 = __ldg(&g_val[p + 2]),    v3 = __ldg(&g_val[p + 3]);
        float2 a0 = *(const float2*)&x[c0 * 64 + 2 * lane];
        float2 a1 = *(const float2*)&x[c1 * 64 + 2 * lane];
        float2 a2 = *(const float2*)&x[c2 * 64 + 2 * lane];
        float2 a3 = *(const float2*)&x[c3 * 64 + 2 * lane];
        acc.x = fmaf(v0, a0.x, acc.x); acc.y = fmaf(v0, a0.y, acc.y);
        acc.x = fmaf(v1, a1.x, acc.x); acc.y = fmaf(v1, a1.y, acc.y);
        acc.x = fmaf(v2, a2.x, acc.x); acc.y = fmaf(v2, a2.y, acc.y);
        acc.x = fmaf(v3, a3.x, acc.x); acc.y = fmaf(v3, a3.y, acc.y);
    }
    for (; p < e; ++p) {
        int c0 = __ldg(&g_colIdx[p]); float v0 = __ldg(&g_val[p]);
        float2 a = *(const float2*)&x[c0 * 64 + 2 * lane];
        acc.x = fmaf(v0, a.x, acc.x); acc.y = fmaf(v0, a.y, acc.y);
    }
    *(float2*)&g_Hcat[w * DIN + 2 * lane]      = xv0;
    *(float2*)&g_Hcat[w * DIN + 64 + 2 * lane] = acc;
}

// hop 2: src = Hcat[:,64:128], dst = Hcat[:,128:192]
__global__ void k_spmm2() {
    int w = (blockIdx.x * blockDim.x + threadIdx.x) >> 5;
    int lane = threadIdx.x & 31;
    if (w >= N_NODES) return;
    float2 acc = *(const float2*)&g_Hcat[w * DIN + 64 + 2 * lane];
    int s = g_rowPtr[w], e = g_rowPtr[w + 1];
    int p = s;
    for (; p + 3 < e; p += 4) {
        int   c0 = __ldg(&g_colIdx[p]),     c1 = __ldg(&g_colIdx[p + 1]);
        int   c2 = __ldg(&g_colIdx[p + 2]), c3 = __ldg(&g_colIdx[p + 3]);
        float v0 = __ldg(&g_val[p]),        v1 = __ldg(&g_val[p + 1]);
        float v2 = __ldg(&g_val[p + 2]),    v3 = __ldg(&g_val[p + 3]);
        float2 a0 = *(const float2*)&g_Hcat[c0 * DIN + 64 + 2 * lane];
        float2 a1 = *(const float2*)&g_Hcat[c1 * DIN + 64 + 2 * lane];
        float2 a2 = *(const float2*)&g_Hcat[c2 * DIN + 64 + 2 * lane];
        float2 a3 = *(const float2*)&g_Hcat[c3 * DIN + 64 + 2 * lane];
        acc.x = fmaf(v0, a0.x, acc.x); acc.y = fmaf(v0, a0.y, acc.y);
        acc.x = fmaf(v1, a1.x, acc.x); acc.y = fmaf(v1, a1.y, acc.y);
        acc.x = fmaf(v2, a2.x, acc.x); acc.y = fmaf(v2, a2.y, acc.y);
        acc.x = fmaf(v3, a3.x, acc.x); acc.y = fmaf(v3, a3.y, acc.y);
    }
    for (; p < e; ++p) {
        int c0 = __ldg(&g_colIdx[p]); float v0 = __ldg(&g_val[p]);
        float2 a = *(const float2*)&g_Hcat[c0 * DIN + 64 + 2 * lane];
        acc.x = fmaf(v0, a.x, acc.x); acc.y = fmaf(v0, a.y, acc.y);
    }
    *(float2*)&g_Hcat[w * DIN + 128 + 2 * lane] = acc;
}

// H-tile = Hcat @ (mask(W)/sigma)^T + b (mask folded into Klim).
// Epilogue: BN1 col sums + per-graph raw sum/max/min atomics. No H store.
__global__ void k_gemm(const float* __restrict__ W, const float* __restrict__ bias,
                       const int* __restrict__ batch) {
    const int m0 = blockIdx.x * 64;
    const int n0 = blockIdx.y * 64;
    const int Klim = 64 * (blockIdx.y + 1);
    __shared__ float As[32][65];
    __shared__ float Bs[32][65];
    __shared__ float s_s[64], s_ss[64];
    const int tid = threadIdx.x;                // 256
    const int tx = tid & 15, ty = tid >> 4;
    const float invSig = 1.0f / g_sigma;
    float acc[4][4] = {};
    for (int k0 = 0; k0 < Klim; k0 += 32) {
#pragma unroll
        for (int r = 0; r < 8; ++r) {
            int e = tid + r * 256;
            int m = e >> 5, k = e & 31;
            As[k][m] = g_Hcat[(m0 + m) * DIN + k0 + k];
            Bs[k][m] = W[(n0 + m) * DIN + k0 + k] * invSig;
        }
        __syncthreads();
#pragma unroll
        for (int k = 0; k < 32; ++k) {
            float a[4], bb[4];
#pragma unroll
            for (int j = 0; j < 4; ++j) { a[j] = As[k][ty * 4 + j]; bb[j] = Bs[k][tx * 4 + j]; }
#pragma unroll
            for (int i = 0; i < 4; ++i)
#pragma unroll
                for (int j = 0; j < 4; ++j) acc[i][j] = fmaf(a[i], bb[j], acc[i][j]);
        }
        __syncthreads();
    }
    if (tid < 64) { s_s[tid] = 0.f; s_ss[tid] = 0.f; }
    int gid[4];
#pragma unroll
    for (int i = 0; i < 4; ++i) gid[i] = batch[m0 + ty * 4 + i];
    __syncthreads();
#pragma unroll
    for (int j = 0; j < 4; ++j) {
        int n = n0 + tx * 4 + j;
        float bv = bias[n];
        float v[4];
        float cs = 0.f, css = 0.f;
#pragma unroll
        for (int i = 0; i < 4; ++i) {
            v[i] = acc[i][j] + bv;
            cs += v[i]; css += v[i] * v[i];
        }
        atomicAdd(&s_s[tx * 4 + j], cs);
        atomicAdd(&s_ss[tx * 4 + j], css);
        // per-graph run-grouped raw stats
        float sm = v[0], mx = v[0], mn = v[0];
#pragma unroll
        for (int i = 1; i < 4; ++i) {
            if (gid[i] != gid[i - 1]) {
                atomicAdd(&g_gsum[gid[i - 1] * DOUT + n], sm);
                atomicMax(&g_gmaxi[gid[i - 1] * DOUT + n], f2o(mx));
                atomicMin(&g_gmini[gid[i - 1] * DOUT + n], f2o(mn));
                sm = v[i]; mx = v[i]; mn = v[i];
            } else {
                sm += v[i]; mx = fmaxf(mx, v[i]); mn = fminf(mn, v[i]);
            }
        }
        atomicAdd(&g_gsum[gid[3] * DOUT + n], sm);
        atomicMax(&g_gmaxi[gid[3] * DOUT + n], f2o(mx));
        atomicMin(&g_gmini[gid[3] * DOUT + n], f2o(mn));
    }
    __syncthreads();
    if (tid < 64) {
        atomicAdd(&g_sum[n0 + tid], s_s[tid]);
        atomicAdd(&g_sumsq[n0 + tid], s_ss[tid]);
    }
}

// pool-finalize + bn2 + fc1 + fc2 + fc3 + log_softmax + scratch re-zero
// 16 blocks x 384 threads, 4 graphs per block
__global__ void k_funnel(const int* __restrict__ batch,
                         const float* __restrict__ g1, const float* __restrict__ be1,
                         const float* __restrict__ g2, const float* __restrict__ be2,
                         const float* __restrict__ w1, const float* __restrict__ b1,
                         const float* __restrict__ w2, const float* __restrict__ b2,
                         const float* __restrict__ w3, const float* __restrict__ b3,
                         float* __restrict__ out) {
    __shared__ int   s_seg[G_GRAPHS + 1];
    __shared__ float s_cnt[G_GRAPHS];
    __shared__ float sx[4][D3];
    __shared__ float a1s[4][H1DIM];
    __shared__ float a2s[4][H2DIM];
    int tid = threadIdx.x;                      // 384
    int r0 = blockIdx.x * 4;

    if (tid <= G_GRAPHS) {
        int lo = 0, hi = N_NODES;
        while (lo < hi) {
            int mid = (lo + hi) >> 1;
            if (batch[mid] < tid) lo = mid + 1; else hi = mid;
        }
        s_seg[tid] = lo;
    }
    __syncthreads();
    if (tid < G_GRAPHS) s_cnt[tid] = (float)(s_seg[tid + 1] - s_seg[tid]);
    __syncthreads();

    // build Hg values on the fly per column; bn2 stats + stash our 4 rows
    for (int c = tid; c < D3; c += 384) {
        int cc = c % DOUT;
        int type = c / DOUT;                    // 0=avg 1=sum 2=max
        float mu1 = g_sum[cc] * (1.0f / N_NODES);
        float var1 = g_sumsq[cc] * (1.0f / N_NODES) - mu1 * mu1;
        float rs1 = rsqrtf(var1 + BN_EPS);
        float a = g1[cc] * rs1;
        float off = be1[cc] - a * mu1;
        float s = 0.f, ss = 0.f;
        for (int g = 0; g < G_GRAPHS; ++g) {
            float val;
            if (type < 2) {
                float sv = a * g_gsum[g * DOUT + cc] + s_cnt[g] * off;
                val = (type == 0) ? sv / fmaxf(s_cnt[g], 1.f) : sv;
            } else {
                float ext = (a >= 0.f) ? o2f(g_gmaxi[g * DOUT + cc])
                                       : o2f(g_gmini[g * DOUT + cc]);
                val = a * ext + off;
            }
            s += val; ss += val * val;
            int r = g - r0;
            if ((unsigned)r < 4u) sx[r][c] = val;
        }
        float mu2 = s * (1.0f / G_GRAPHS);
        float var2 = ss * (1.0f / G_GRAPHS) - mu2 * mu2;
        float rs2 = rsqrtf(var2 + BN_EPS);
        float ga2 = g2[c], bb2 = be2[c];
#pragma unroll
        for (int r = 0; r < 4; ++r)
            sx[r][c] = ga2 * (sx[r][c] - mu2) * rs2 + bb2;
    }
    __syncthreads();
    // fc1: 384 outs
    {
        int o = tid;
        float a0 = b1[o], a1 = a0, a2 = a0, a3 = a0;
        const float4* wr = (const float4*)&w1[o * D3];
#pragma unroll 4
        for (int k4 = 0; k4 < D3 / 4; ++k4) {
            float4 w = wr[k4];
            int k = k4 * 4;
            a0 += w.x * sx[0][k] + w.y * sx[0][k + 1] + w.z * sx[0][k + 2] + w.w * sx[0][k + 3];
            a1 += w.x * sx[1][k] + w.y * sx[1][k + 1] + w.z * sx[1][k + 2] + w.w * sx[1][k + 3];
            a2 += w.x * sx[2][k] + w.y * sx[2][k + 1] + w.z * sx[2][k + 2] + w.w * sx[2][k + 3];
            a3 += w.x * sx[3][k] + w.y * sx[3][k + 1] + w.z * sx[3][k + 2] + w.w * sx[3][k + 3];
        }
        a1s[0][o] = fmaxf(a0, 0.f);
        a1s[1][o] = fmaxf(a1, 0.f);
        a1s[2][o] = fmaxf(a2, 0.f);
        a1s[3][o] = fmaxf(a3, 0.f);
    }
    __syncthreads();
    // fc2: 192 outs
    if (tid < H2DIM) {
        int o = tid;
        float a0 = b2[o], a1 = a0, a2 = a0, a3 = a0;
        const float4* wr = (const float4*)&w2[o * H1DIM];
#pragma unroll 4
        for (int k4 = 0; k4 < H1DIM / 4; ++k4) {
            float4 w = wr[k4];
            int k = k4 * 4;
            a0 += w.x * a1s[0][k] + w.y * a1s[0][k + 1] + w.z * a1s[0][k + 2] + w.w * a1s[0][k + 3];
            a1 += w.x * a1s[1][k] + w.y * a1s[1][k + 1] + w.z * a1s[1][k + 2] + w.w * a1s[1][k + 3];
            a2 += w.x * a1s[2][k] + w.y * a1s[2][k + 1] + w.z * a1s[2][k + 2] + w.w * a1s[2][k + 3];
            a3 += w.x * a1s[3][k] + w.y * a1s[3][k + 1] + w.z * a1s[3][k + 2] + w.w * a1s[3][k + 3];
        }
        a2s[0][o] = fmaxf(a0, 0.f);
        a2s[1][o] = fmaxf(a1, 0.f);
        a2s[2][o] = fmaxf(a2, 0.f);
        a2s[3][o] = fmaxf(a3, 0.f);
    }
    __syncthreads();
    // fc3 + log_softmax: warp w handles graph r0+w
    if (tid < 128) {
        int wrp = tid >> 5, lane = tid & 31;
        float z = -CUDART_INF_F;
        if (lane < NCLS) {
            z = b3[lane];
            const float* wr = &w3[lane * H2DIM];
            for (int k = 0; k < H2DIM; ++k) z = fmaf(wr[k], a2s[wrp][k], z);
        }
        float mx = z;
#pragma unroll
        for (int off = 16; off; off >>= 1) mx = fmaxf(mx, __shfl_xor_sync(0xffffffff, mx, off));
        float ex = (lane < NCLS) ? expf(z - mx) : 0.f;
        float sm = ex;
#pragma unroll
        for (int off = 16; off; off >>= 1) sm += __shfl_xor_sync(0xffffffff, sm, off);
        if (lane < NCLS) out[(r0 + wrp) * NCLS + lane] = z - mx - logf(sm);
    }
    // tail: re-zero scratch for next replay
    int gidx = blockIdx.x * 384 + tid;
    for (int i = gidx; i < N_NODES; i += 16 * 384) {
        g_deg[i] = 0.f;
        g_rowCnt[i] = 0;
    }
}

// ---------------- launch ----------------
extern "C" void kernel_launch(void* const* d_in, const int* in_sizes, int n_in,
                              void* d_out, int out_size) {
    const float* x     = (const float*)d_in[0];
    const int*   ei    = (const int*)d_in[1];
    const int*   batch = (const int*)d_in[2];
    const float* Wo    = (const float*)d_in[3];
    const float* b     = (const float*)d_in[4];
    const float* u     = (const float*)d_in[5];
    const float* bn1g  = (const float*)d_in[6];
    const float* bn1b  = (const float*)d_in[7];
    const float* bn2g  = (const float*)d_in[8];
    const float* bn2b  = (const float*)d_in[9];
    const float* w1    = (const float*)d_in[10];
    const float* b1    = (const float*)d_in[11];
    const float* w2    = (const float*)d_in[12];
    const float* b2    = (const float*)d_in[13];
    const float* w3    = (const float*)d_in[14];
    const float* b3    = (const float*)d_in[15];
    float*       out   = (float*)d_out;

    k_degree<<<N_EDGES / 256, 256>>>(ei);
    k_scan<<<1, 1024>>>(Wo, u);
    k_build<<<N_EDGES / 256, 256>>>(ei);
    k_spmm1<<<N_NODES * 32 / 256, 256>>>(x);
    k_spmm2<<<N_NODES * 32 / 256, 256>>>();
    k_gemm<<<dim3(N_NODES / 64, DOUT / 64), 256>>>(Wo, b, batch);
    k_funnel<<<16, 384>>>(batch, bn1g, bn1b, bn2g, bn2b, w1, b1, w2, b2, w3, b3, out);
}

// round 9
// speedup vs baseline: 1.2620x; 1.2620x over previous
#include <cuda_runtime.h>
#include <math_constants.h>

// ---------------- problem constants (fixed shapes) ----------------
#define N_NODES  8192
#define N_EDGES  262144
#define IN_C     64
#define DIN      192          // IN_C * K
#define DOUT     192          // OUT_C * K
#define G_GRAPHS 64
#define D3       576          // 3 * DOUT
#define H1DIM    384
#define H2DIM    192
#define NCLS     10
#define BN_EPS   1e-5f

// ---------------- device scratch ----------------
__device__ float g_deg[N_NODES];        // zeroed by funnel tail
__device__ int   g_rowCnt[N_NODES];     // zeroed by funnel tail
__device__ float g_dinv[N_NODES];
__device__ int   g_rowPtr[N_NODES + 1];
__device__ unsigned long long g_cv[N_EDGES];   // packed (val<<32 | col)
__device__ float g_Hcat[N_NODES * DIN]; // [x | Lx | L^2 x]
__device__ float g_H[N_NODES * DOUT];   // after masked linear (+bias)
__device__ float g_sigma;
__device__ float g_sum[DOUT], g_sumsq[DOUT];   // BN1 stats (zeroed by funnel tail)
__device__ float g_Hg[G_GRAPHS * D3];   // [avg | sum | max] per graph

// ---------------- kernels ----------------

__global__ void k_degree(const int* __restrict__ ei) {
    int e = blockIdx.x * blockDim.x + threadIdx.x;
    if (e < N_EDGES) atomicAdd(&g_deg[ei[e]], 1.0f);
}

// dinv + exclusive scan (warp-shuffle) + spectral sigma, one block of 1024
__global__ void k_scan(const float* __restrict__ W, const float* __restrict__ u) {
    __shared__ int   wsum[32];
    __shared__ float fred[256];
    int t = threadIdx.x, lane = t & 31, wid = t >> 5;
    int base = t * 8;
    int loc[8]; int s = 0;
#pragma unroll
    for (int j = 0; j < 8; ++j) {
        float d = g_deg[base + j];
        g_dinv[base + j] = (d > 0.f) ? rsqrtf(fmaxf(d, 1.f)) : 0.f;
        loc[j] = s; s += (int)d;
    }
    int isc = s;
#pragma unroll
    for (int off = 1; off < 32; off <<= 1) {
        int v = __shfl_up_sync(0xffffffff, isc, off);
        if (lane >= off) isc += v;
    }
    if (lane == 31) wsum[wid] = isc;
    __syncthreads();
    if (wid == 0) {
        int v = wsum[lane];
        int sc = v;
#pragma unroll
        for (int off = 1; off < 32; off <<= 1) {
            int q = __shfl_up_sync(0xffffffff, sc, off);
            if (lane >= off) sc += q;
        }
        wsum[lane] = sc - v;
    }
    __syncthreads();
    int tbase = wsum[wid] + (isc - s);
#pragma unroll
    for (int j = 0; j < 8; ++j) g_rowPtr[base + j] = tbase + loc[j];
    if (t == 1023) g_rowPtr[N_NODES] = tbase + s;

    float vsq = 0.f;
    if (t < DIN) {
        float v = 0.f;
        for (int i = 0; i < DOUT; ++i) v = fmaf(W[i * DIN + t], u[i], v);
        vsq = v * v;
    }
    if (t < 256) fred[t] = vsq;
    __syncthreads();
    for (int off = 128; off; off >>= 1) {
        if (t < 256 && t < off) fred[t] += fred[t + off];
        __syncthreads();
    }
    if (t == 0) {
        float ns = fred[0];
        g_sigma = ns / (sqrtf(ns) + 1e-12f);
    }
}

// CSR fill: one packed 8B store per edge
__global__ void k_build(const int* __restrict__ ei) {
    int e = blockIdx.x * blockDim.x + threadIdx.x;
    if (e >= N_EDGES) return;
    int r = ei[e];
    int c = ei[N_EDGES + e];
    float v = -g_dinv[r] * g_dinv[c];
    int pos = g_rowPtr[r] + atomicAdd(&g_rowCnt[r], 1);
    g_cv[pos] = ((unsigned long long)__float_as_uint(v) << 32) | (unsigned int)c;
}

// hop 1: Hcat[:,0:64]=x, Hcat[:,64:128]=x+L_off@x  (warp/row, 4-edge batched)
__global__ void __launch_bounds__(256, 4) k_spmm1(const float* __restrict__ x) {
    int w = (blockIdx.x * blockDim.x + threadIdx.x) >> 5;
    int lane = threadIdx.x & 31;
    float2 xv0 = *(const float2*)&x[w * 64 + 2 * lane];
    float2 acc = xv0;
    int s = g_rowPtr[w], e = g_rowPtr[w + 1];
    int p = s;
    for (; p + 3 < e; p += 4) {
        unsigned long long cv0 = __ldg(&g_cv[p]);
        unsigned long long cv1 = __ldg(&g_cv[p + 1]);
        unsigned long long cv2 = __ldg(&g_cv[p + 2]);
        unsigned long long cv3 = __ldg(&g_cv[p + 3]);
        float2 a0 = *(const float2*)&x[(int)(cv0 & 0xffffffffu) * 64 + 2 * lane];
        float2 a1 = *(const float2*)&x[(int)(cv1 & 0xffffffffu) * 64 + 2 * lane];
        float2 a2 = *(const float2*)&x[(int)(cv2 & 0xffffffffu) * 64 + 2 * lane];
        float2 a3 = *(const float2*)&x[(int)(cv3 & 0xffffffffu) * 64 + 2 * lane];
        float v0 = __uint_as_float((unsigned)(cv0 >> 32));
        float v1 = __uint_as_float((unsigned)(cv1 >> 32));
        float v2 = __uint_as_float((unsigned)(cv2 >> 32));
        float v3 = __uint_as_float((unsigned)(cv3 >> 32));
        acc.x = fmaf(v0, a0.x, acc.x); acc.y = fmaf(v0, a0.y, acc.y);
        acc.x = fmaf(v1, a1.x, acc.x); acc.y = fmaf(v1, a1.y, acc.y);
        acc.x = fmaf(v2, a2.x, acc.x); acc.y = fmaf(v2, a2.y, acc.y);
        acc.x = fmaf(v3, a3.x, acc.x); acc.y = fmaf(v3, a3.y, acc.y);
    }
    for (; p < e; ++p) {
        unsigned long long cv = __ldg(&g_cv[p]);
        float v = __uint_as_float((unsigned)(cv >> 32));
        float2 a = *(const float2*)&x[(int)(cv & 0xffffffffu) * 64 + 2 * lane];
        acc.x = fmaf(v, a.x, acc.x); acc.y = fmaf(v, a.y, acc.y);
    }
    *(float2*)&g_Hcat[w * DIN + 2 * lane]      = xv0;
    *(float2*)&g_Hcat[w * DIN + 64 + 2 * lane] = acc;
}

// hop 2: src = Hcat[:,64:128], dst = Hcat[:,128:192]
__global__ void __launch_bounds__(256, 4) k_spmm2() {
    int w = (blockIdx.x * blockDim.x + threadIdx.x) >> 5;
    int lane = threadIdx.x & 31;
    const float* src = &g_Hcat[64 + 2 * lane];
    float2 acc = *(const float2*)&src[w * DIN];
    int s = g_rowPtr[w], e = g_rowPtr[w + 1];
    int p = s;
    for (; p + 3 < e; p += 4) {
        unsigned long long cv0 = __ldg(&g_cv[p]);
        unsigned long long cv1 = __ldg(&g_cv[p + 1]);
        unsigned long long cv2 = __ldg(&g_cv[p + 2]);
        unsigned long long cv3 = __ldg(&g_cv[p + 3]);
        float2 a0 = *(const float2*)&src[(int)(cv0 & 0xffffffffu) * DIN];
        float2 a1 = *(const float2*)&src[(int)(cv1 & 0xffffffffu) * DIN];
        float2 a2 = *(const float2*)&src[(int)(cv2 & 0xffffffffu) * DIN];
        float2 a3 = *(const float2*)&src[(int)(cv3 & 0xffffffffu) * DIN];
        float v0 = __uint_as_float((unsigned)(cv0 >> 32));
        float v1 = __uint_as_float((unsigned)(cv1 >> 32));
        float v2 = __uint_as_float((unsigned)(cv2 >> 32));
        float v3 = __uint_as_float((unsigned)(cv3 >> 32));
        acc.x = fmaf(v0, a0.x, acc.x); acc.y = fmaf(v0, a0.y, acc.y);
        acc.x = fmaf(v1, a1.x, acc.x); acc.y = fmaf(v1, a1.y, acc.y);
        acc.x = fmaf(v2, a2.x, acc.x); acc.y = fmaf(v2, a2.y, acc.y);
        acc.x = fmaf(v3, a3.x, acc.x); acc.y = fmaf(v3, a3.y, acc.y);
    }
    for (; p < e; ++p) {
        unsigned long long cv = __ldg(&g_cv[p]);
        float v = __uint_as_float((unsigned)(cv >> 32));
        float2 a = *(const float2*)&src[(int)(cv & 0xffffffffu) * DIN];
        acc.x = fmaf(v, a.x, acc.x); acc.y = fmaf(v, a.y, acc.y);
    }
    *(float2*)&g_Hcat[w * DIN + 128 + 2 * lane] = acc;
}

// H = Hcat @ (mask(W)/sigma)^T + b, mask folded into Klim.
// Fused BN1 column-stat accumulation via smem + global atomics.
__global__ void k_gemm(const float* __restrict__ W, const float* __restrict__ bias) {
    const int m0 = blockIdx.x * 64;
    const int n0 = blockIdx.y * 64;
    const int Klim = 64 * (blockIdx.y + 1);
    __shared__ float As[32][65];
    __shared__ float Bs[32][65];
    __shared__ float s_s[64], s_ss[64];
    const int tid = threadIdx.x;                // 256
    const int tx = tid & 15, ty = tid >> 4;
    const float invSig = 1.0f / g_sigma;
    float acc[4][4] = {};
    for (int k0 = 0; k0 < Klim; k0 += 32) {
#pragma unroll
        for (int r = 0; r < 8; ++r) {
            int e = tid + r * 256;
            int m = e >> 5, k = e & 31;
            As[k][m] = g_Hcat[(m0 + m) * DIN + k0 + k];
            Bs[k][m] = W[(n0 + m) * DIN + k0 + k] * invSig;
        }
        __syncthreads();
#pragma unroll
        for (int k = 0; k < 32; ++k) {
            float a[4], bb[4];
#pragma unroll
            for (int j = 0; j < 4; ++j) { a[j] = As[k][ty * 4 + j]; bb[j] = Bs[k][tx * 4 + j]; }
#pragma unroll
            for (int i = 0; i < 4; ++i)
#pragma unroll
                for (int j = 0; j < 4; ++j) acc[i][j] = fmaf(a[i], bb[j], acc[i][j]);
        }
        __syncthreads();
    }
    if (tid < 64) { s_s[tid] = 0.f; s_ss[tid] = 0.f; }
    __syncthreads();
#pragma unroll
    for (int j = 0; j < 4; ++j) {
        int n = n0 + tx * 4 + j;
        float bv = bias[n];
        float cs = 0.f, css = 0.f;
#pragma unroll
        for (int i = 0; i < 4; ++i) {
            int m = m0 + ty * 4 + i;
            float v = acc[i][j] + bv;
            g_H[m * DOUT + n] = v;
            cs += v; css += v * v;
        }
        atomicAdd(&s_s[tx * 4 + j], cs);
        atomicAdd(&s_ss[tx * 4 + j], css);
    }
    __syncthreads();
    if (tid < 64) {
        atomicAdd(&g_sum[n0 + tid], s_s[tid]);
        atomicAdd(&g_sumsq[n0 + tid], s_ss[tid]);
    }
}

// BN1(apply) + segment avg/sum/max; 384 threads = 2 row-halves per column
__global__ void k_pool(const int* __restrict__ batch,
                       const float* __restrict__ gamma, const float* __restrict__ beta) {
    __shared__ int sse[2];
    __shared__ float s_sum[DOUT], s_max[DOUT];
    int g = blockIdx.x;
    int t = threadIdx.x;                        // 384
    int c = t % DOUT, h = t / DOUT;
    if (t < 2) {
        int target = g + t;
        int lo = 0, hi = N_NODES;
        while (lo < hi) {
            int mid = (lo + hi) >> 1;
            if (batch[mid] < target) lo = mid + 1; else hi = mid;
        }
        sse[t] = lo;
    }
    __syncthreads();
    int s = sse[0], e = sse[1];
    float mu = g_sum[c] * (1.0f / N_NODES);
    float var = g_sumsq[c] * (1.0f / N_NODES) - mu * mu;
    float rs = rsqrtf(var + BN_EPS);
    float ga = gamma[c], be = beta[c];
    float a = ga * rs, off = be - a * mu;       // v = a*h + off
    float sum = 0.f, mx = -CUDART_INF_F;
#pragma unroll 4
    for (int r = s + h; r < e; r += 2) {
        float v = fmaf(a, g_H[r * DOUT + c], off);
        sum += v;
        mx = fmaxf(mx, v);
    }
    if (h == 1) { s_sum[c] = sum; s_max[c] = mx; }
    __syncthreads();
    if (h == 0) {
        sum += s_sum[c];
        mx = fmaxf(mx, s_max[c]);
        float cnt = (float)(e - s);
        g_Hg[g * D3 + c]            = sum / fmaxf(cnt, 1.f);
        g_Hg[g * D3 + DOUT + c]     = sum;
        g_Hg[g * D3 + 2 * DOUT + c] = mx;
    }
}

// bn2 + fc1 + fc2 + fc3 + log_softmax + scratch re-zero (16 blocks x 384)
__global__ void k_funnel(const float* __restrict__ g2, const float* __restrict__ be2,
                         const float* __restrict__ w1, const float* __restrict__ b1,
                         const float* __restrict__ w2, const float* __restrict__ b2,
                         const float* __restrict__ w3, const float* __restrict__ b3,
                         float* __restrict__ out) {
    __shared__ float smu[D3], srs[D3];
    __shared__ float sx[4][D3];
    __shared__ float a1s[4][H1DIM];
    __shared__ float a2s[4][H2DIM];
    int tid = threadIdx.x;                      // 384
    int r0 = blockIdx.x * 4;

    for (int c = tid; c < D3; c += 384) {
        float s = 0.f, ss = 0.f;
        for (int r = 0; r < G_GRAPHS; ++r) {
            float v = g_Hg[r * D3 + c];
            s += v; ss += v * v;
        }
        float mu = s * (1.0f / G_GRAPHS);
        float var = ss * (1.0f / G_GRAPHS) - mu * mu;
        smu[c] = mu;
        srs[c] = rsqrtf(var + BN_EPS);
    }
    __syncthreads();
    for (int e = tid; e < 4 * D3; e += 384) {
        int r = e / D3, c = e % D3;
        sx[r][c] = g2[c] * (g_Hg[(r0 + r) * D3 + c] - smu[c]) * srs[c] + be2[c];
    }
    __syncthreads();
    {
        int o = tid;
        float a0 = b1[o], a1 = a0, a2 = a0, a3 = a0;
        const float4* wr = (const float4*)&w1[o * D3];
#pragma unroll 4
        for (int k4 = 0; k4 < D3 / 4; ++k4) {
            float4 w = wr[k4];
            int k = k4 * 4;
            a0 += w.x * sx[0][k] + w.y * sx[0][k + 1] + w.z * sx[0][k + 2] + w.w * sx[0][k + 3];
            a1 += w.x * sx[1][k] + w.y * sx[1][k + 1] + w.z * sx[1][k + 2] + w.w * sx[1][k + 3];
            a2 += w.x * sx[2][k] + w.y * sx[2][k + 1] + w.z * sx[2][k + 2] + w.w * sx[2][k + 3];
            a3 += w.x * sx[3][k] + w.y * sx[3][k + 1] + w.z * sx[3][k + 2] + w.w * sx[3][k + 3];
        }
        a1s[0][o] = fmaxf(a0, 0.f);
        a1s[1][o] = fmaxf(a1, 0.f);
        a1s[2][o] = fmaxf(a2, 0.f);
        a1s[3][o] = fmaxf(a3, 0.f);
    }
    __syncthreads();
    if (tid < H2DIM) {
        int o = tid;
        float a0 = b2[o], a1 = a0, a2 = a0, a3 = a0;
        const float4* wr = (const float4*)&w2[o * H1DIM];
#pragma unroll 4
        for (int k4 = 0; k4 < H1DIM / 4; ++k4) {
            float4 w = wr[k4];
            int k = k4 * 4;
            a0 += w.x * a1s[0][k] + w.y * a1s[0][k + 1] + w.z * a1s[0][k + 2] + w.w * a1s[0][k + 3];
            a1 += w.x * a1s[1][k] + w.y * a1s[1][k + 1] + w.z * a1s[1][k + 2] + w.w * a1s[1][k + 3];
            a2 += w.x * a1s[2][k] + w.y * a1s[2][k + 1] + w.z * a1s[2][k + 2] + w.w * a1s[2][k + 3];
            a3 += w.x * a1s[3][k] + w.y * a1s[3][k + 1] + w.z * a1s[3][k + 2] + w.w * a1s[3][k + 3];
        }
        a2s[0][o] = fmaxf(a0, 0.f);
        a2s[1][o] = fmaxf(a1, 0.f);
        a2s[2][o] = fmaxf(a2, 0.f);
        a2s[3][o] = fmaxf(a3, 0.f);
    }
    __syncthreads();
    if (tid < 128) {
        int wrp = tid >> 5, lane = tid & 31;
        float z = -CUDART_INF_F;
        if (lane < NCLS) {
            z = b3[lane];
            const float* wr = &w3[lane * H2DIM];
            for (int k = 0; k < H2DIM; ++k) z = fmaf(wr[k], a2s[wrp][k], z);
        }
        float mx = z;
#pragma unroll
        for (int off = 16; off; off >>= 1) mx = fmaxf(mx, __shfl_xor_sync(0xffffffff, mx, off));
        float ex = (lane < NCLS) ? expf(z - mx) : 0.f;
        float sm = ex;
#pragma unroll
        for (int off = 16; off; off >>= 1) sm += __shfl_xor_sync(0xffffffff, sm, off);
        if (lane < NCLS) out[(r0 + wrp) * NCLS + lane] = z - mx - logf(sm);
    }
    int gidx = blockIdx.x * 384 + tid;
    for (int i = gidx; i < N_NODES; i += 16 * 384) {
        g_deg[i] = 0.f;
        g_rowCnt[i] = 0;
    }
    if (gidx < DOUT) { g_sum[gidx] = 0.f; g_sumsq[gidx] = 0.f; }
}

// ---------------- launch ----------------
extern "C" void kernel_launch(void* const* d_in, const int* in_sizes, int n_in,
                              void* d_out, int out_size) {
    const float* x     = (const float*)d_in[0];
    const int*   ei    = (const int*)d_in[1];
    const int*   batch = (const int*)d_in[2];
    const float* Wo    = (const float*)d_in[3];
    const float* b     = (const float*)d_in[4];
    const float* u     = (const float*)d_in[5];
    const float* bn1g  = (const float*)d_in[6];
    const float* bn1b  = (const float*)d_in[7];
    const float* bn2g  = (const float*)d_in[8];
    const float* bn2b  = (const float*)d_in[9];
    const float* w1    = (const float*)d_in[10];
    const float* b1    = (const float*)d_in[11];
    const float* w2    = (const float*)d_in[12];
    const float* b2    = (const float*)d_in[13];
    const float* w3    = (const float*)d_in[14];
    const float* b3    = (const float*)d_in[15];
    float*       out   = (float*)d_out;

    k_degree<<<N_EDGES / 256, 256>>>(ei);
    k_scan<<<1, 1024>>>(Wo, u);
    k_build<<<N_EDGES / 256, 256>>>(ei);
    k_spmm1<<<N_NODES * 32 / 256, 256>>>(x);
    k_spmm2<<<N_NODES * 32 / 256, 256>>>();
    k_gemm<<<dim3(N_NODES / 64, DOUT / 64), 256>>>(Wo, b);
    k_pool<<<G_GRAPHS, 384>>>(batch, bn1g, bn1b);
    k_funnel<<<16, 384>>>(bn2g, bn2b, w1, b1, w2, b2, w3, b3, out);
}

// round 11
// speedup vs baseline: 1.2726x; 1.0084x over previous
#include <cuda_runtime.h>
#include <math_constants.h>

// ---------------- problem constants (fixed shapes) ----------------
#define N_NODES  8192
#define N_EDGES  262144
#define IN_C     64
#define DIN      192          // IN_C * K
#define DOUT     192          // OUT_C * K
#define G_GRAPHS 64
#define D3       576          // 3 * DOUT
#define H1DIM    384
#define H2DIM    192
#define NCLS     10
#define BN_EPS   1e-5f

// ---------------- device scratch ----------------
__device__ float g_deg[N_NODES];        // zeroed by funnel tail
__device__ int   g_rowCnt[N_NODES];     // zeroed by funnel tail
__device__ float g_dinv[N_NODES];
__device__ int   g_rowPtr[N_NODES + 1];
__device__ unsigned long long g_cv[N_EDGES];   // packed (val<<32 | col)
__device__ float g_Hcat[N_NODES * DIN]; // [x | Lx | L^2 x]
__device__ float g_H[N_NODES * DOUT];   // after masked linear (+bias)
__device__ float g_sigma;
__device__ float g_sum[DOUT], g_sumsq[DOUT];   // BN1 stats (zeroed by funnel tail)
__device__ float g_Hg[G_GRAPHS * D3];   // [avg | sum | max] per graph

// ---------------- kernels ----------------

__global__ void k_degree(const int* __restrict__ ei) {
    int e = blockIdx.x * blockDim.x + threadIdx.x;
    if (e < N_EDGES) atomicAdd(&g_deg[ei[e]], 1.0f);
}

// dinv + exclusive scan (warp-shuffle) + spectral sigma, one block of 1024
__global__ void k_scan(const float* __restrict__ W, const float* __restrict__ u) {
    __shared__ int   wsum[32];
    __shared__ float fred[256];
    int t = threadIdx.x, lane = t & 31, wid = t >> 5;
    int base = t * 8;
    int loc[8]; int s = 0;
#pragma unroll
    for (int j = 0; j < 8; ++j) {
        float d = g_deg[base + j];
        g_dinv[base + j] = (d > 0.f) ? rsqrtf(fmaxf(d, 1.f)) : 0.f;
        loc[j] = s; s += (int)d;
    }
    int isc = s;
#pragma unroll
    for (int off = 1; off < 32; off <<= 1) {
        int v = __shfl_up_sync(0xffffffff, isc, off);
        if (lane >= off) isc += v;
    }
    if (lane == 31) wsum[wid] = isc;
    __syncthreads();
    if (wid == 0) {
        int v = wsum[lane];
        int sc = v;
#pragma unroll
        for (int off = 1; off < 32; off <<= 1) {
            int q = __shfl_up_sync(0xffffffff, sc, off);
            if (lane >= off) sc += q;
        }
        wsum[lane] = sc - v;
    }
    __syncthreads();
    int tbase = wsum[wid] + (isc - s);
#pragma unroll
    for (int j = 0; j < 8; ++j) g_rowPtr[base + j] = tbase + loc[j];
    if (t == 1023) g_rowPtr[N_NODES] = tbase + s;

    float vsq = 0.f;
    if (t < DIN) {
        float v = 0.f;
        for (int i = 0; i < DOUT; ++i) v = fmaf(W[i * DIN + t], u[i], v);
        vsq = v * v;
    }
    if (t < 256) fred[t] = vsq;
    __syncthreads();
    for (int off = 128; off; off >>= 1) {
        if (t < 256 && t < off) fred[t] += fred[t + off];
        __syncthreads();
    }
    if (t == 0) {
        float ns = fred[0];
        g_sigma = ns / (sqrtf(ns) + 1e-12f);
    }
}

// CSR fill: one packed 8B store per edge
__global__ void k_build(const int* __restrict__ ei) {
    int e = blockIdx.x * blockDim.x + threadIdx.x;
    if (e >= N_EDGES) return;
    int r = ei[e];
    int c = ei[N_EDGES + e];
    float v = -g_dinv[r] * g_dinv[c];
    int pos = g_rowPtr[r] + atomicAdd(&g_rowCnt[r], 1);
    g_cv[pos] = ((unsigned long long)__float_as_uint(v) << 32) | (unsigned int)c;
}

// SpMM body: software-pipelined 4-edge groups (prefetch next cv group before
// issuing current gathers -> cv loads overlap gather latency).
// src is base pointer with lane offset pre-applied; stride in floats.
template <int STRIDE>
__device__ __forceinline__ float2 spmm_row(const float* __restrict__ src,
                                           float2 acc, int s, int e) {
    int n4 = (e - s) >> 2;
    int p = s;
    if (n4 > 0) {
        unsigned long long a0 = __ldg(&g_cv[p]),     a1 = __ldg(&g_cv[p + 1]);
        unsigned long long a2 = __ldg(&g_cv[p + 2]), a3 = __ldg(&g_cv[p + 3]);
        for (int gq = 0; gq < n4; ++gq) {
            unsigned long long b0 = a0, b1 = a1, b2 = a2, b3 = a3;
            p += 4;
            if (gq + 1 < n4) {
                a0 = __ldg(&g_cv[p]);     a1 = __ldg(&g_cv[p + 1]);
                a2 = __ldg(&g_cv[p + 2]); a3 = __ldg(&g_cv[p + 3]);
            }
            float2 x0 = *(const float2*)&src[(int)(b0 & 0xffffffffu) * STRIDE];
            float2 x1 = *(const float2*)&src[(int)(b1 & 0xffffffffu) * STRIDE];
            float2 x2 = *(const float2*)&src[(int)(b2 & 0xffffffffu) * STRIDE];
            float2 x3 = *(const float2*)&src[(int)(b3 & 0xffffffffu) * STRIDE];
            float v0 = __uint_as_float((unsigned)(b0 >> 32));
            float v1 = __uint_as_float((unsigned)(b1 >> 32));
            float v2 = __uint_as_float((unsigned)(b2 >> 32));
            float v3 = __uint_as_float((unsigned)(b3 >> 32));
            acc.x = fmaf(v0, x0.x, acc.x); acc.y = fmaf(v0, x0.y, acc.y);
            acc.x = fmaf(v1, x1.x, acc.x); acc.y = fmaf(v1, x1.y, acc.y);
            acc.x = fmaf(v2, x2.x, acc.x); acc.y = fmaf(v2, x2.y, acc.y);
            acc.x = fmaf(v3, x3.x, acc.x); acc.y = fmaf(v3, x3.y, acc.y);
        }
    }
    for (; p < e; ++p) {
        unsigned long long cv = __ldg(&g_cv[p]);
        float v = __uint_as_float((unsigned)(cv >> 32));
        float2 a = *(const float2*)&src[(int)(cv & 0xffffffffu) * STRIDE];
        acc.x = fmaf(v, a.x, acc.x); acc.y = fmaf(v, a.y, acc.y);
    }
    return acc;
}

// hop 1: Hcat[:,0:64]=x, Hcat[:,64:128]=x+L_off@x  (warp/row)
__global__ void __launch_bounds__(256, 4) k_spmm1(const float* __restrict__ x) {
    int w = (blockIdx.x * blockDim.x + threadIdx.x) >> 5;
    int lane = threadIdx.x & 31;
    const float* src = &x[2 * lane];
    float2 xv0 = *(const float2*)&src[w * 64];
    float2 acc = spmm_row<64>(src, xv0, g_rowPtr[w], g_rowPtr[w + 1]);
    *(float2*)&g_Hcat[w * DIN + 2 * lane]      = xv0;
    *(float2*)&g_Hcat[w * DIN + 64 + 2 * lane] = acc;
}

// hop 2: src = Hcat[:,64:128], dst = Hcat[:,128:192]
__global__ void __launch_bounds__(256, 4) k_spmm2() {
    int w = (blockIdx.x * blockDim.x + threadIdx.x) >> 5;
    int lane = threadIdx.x & 31;
    const float* src = &g_Hcat[64 + 2 * lane];
    float2 acc0 = *(const float2*)&src[w * DIN];
    float2 acc = spmm_row<DIN>(src, acc0, g_rowPtr[w], g_rowPtr[w + 1]);
    *(float2*)&g_Hcat[w * DIN + 128 + 2 * lane] = acc;
}

// H = Hcat @ (mask(W)/sigma)^T + b, mask folded into Klim.
// float4 shared reads (rows padded to 68 floats = 16B-aligned).
// Fused BN1 column-stat accumulation via smem + global atomics.
__global__ void k_gemm(const float* __restrict__ W, const float* __restrict__ bias) {
    const int m0 = blockIdx.x * 64;
    const int n0 = blockIdx.y * 64;
    const int Klim = 64 * (blockIdx.y + 1);
    __shared__ float As[32][68];
    __shared__ float Bs[32][68];
    __shared__ float s_s[64], s_ss[64];
    const int tid = threadIdx.x;                // 256
    const int tx = tid & 15, ty = tid >> 4;
    const float invSig = 1.0f / g_sigma;
    float acc[4][4] = {};
    for (int k0 = 0; k0 < Klim; k0 += 32) {
#pragma unroll
        for (int r = 0; r < 8; ++r) {
            int e = tid + r * 256;
            int m = e >> 5, k = e & 31;
            As[k][m] = g_Hcat[(m0 + m) * DIN + k0 + k];
            Bs[k][m] = W[(n0 + m) * DIN + k0 + k] * invSig;
        }
        __syncthreads();
#pragma unroll
        for (int k = 0; k < 32; ++k) {
            float4 av = *(const float4*)&As[k][ty * 4];
            float4 bv = *(const float4*)&Bs[k][tx * 4];
            float a[4] = {av.x, av.y, av.z, av.w};
            float bb[4] = {bv.x, bv.y, bv.z, bv.w};
#pragma unroll
            for (int i = 0; i < 4; ++i)
#pragma unroll
                for (int j = 0; j < 4; ++j) acc[i][j] = fmaf(a[i], bb[j], acc[i][j]);
        }
        __syncthreads();
    }
    if (tid < 64) { s_s[tid] = 0.f; s_ss[tid] = 0.f; }
    __syncthreads();
#pragma unroll
    for (int j = 0; j < 4; ++j) {
        int n = n0 + tx * 4 + j;
        float bv = bias[n];
        float cs = 0.f, css = 0.f;
#pragma unroll
        for (int i = 0; i < 4; ++i) {
            int m = m0 + ty * 4 + i;
            float v = acc[i][j] + bv;
            g_H[m * DOUT + n] = v;
            cs += v; css += v * v;
        }
        atomicAdd(&s_s[tx * 4 + j], cs);
        atomicAdd(&s_ss[tx * 4 + j], css);
    }
    __syncthreads();
    if (tid < 64) {
        atomicAdd(&g_sum[n0 + tid], s_s[tid]);
        atomicAdd(&g_sumsq[n0 + tid], s_ss[tid]);
    }
}

// BN1(apply) + segment avg/sum/max; 384 threads = 2 row-halves per column
__global__ void k_pool(const int* __restrict__ batch,
                       const float* __restrict__ gamma, const float* __restrict__ beta) {
    __shared__ int sse[2];
    __shared__ float s_sum[DOUT], s_max[DOUT];
    int g = blockIdx.x;
    int t = threadIdx.x;                        // 384
    int c = t % DOUT, h = t / DOUT;
    if (t < 2) {
        int target = g + t;
        int lo = 0, hi = N_NODES;
        while (lo < hi) {
            int mid = (lo + hi) >> 1;
            if (batch[mid] < target) lo = mid + 1; else hi = mid;
        }
        sse[t] = lo;
    }
    __syncthreads();
    int s = sse[0], e = sse[1];
    float mu = g_sum[c] * (1.0f / N_NODES);
    float var = g_sumsq[c] * (1.0f / N_NODES) - mu * mu;
    float rs = rsqrtf(var + BN_EPS);
    float ga = gamma[c], be = beta[c];
    float a = ga * rs, off = be - a * mu;       // v = a*h + off
    float sum = 0.f, mx = -CUDART_INF_F;
#pragma unroll 4
    for (int r = s + h; r < e; r += 2) {
        float v = fmaf(a, g_H[r * DOUT + c], off);
        sum += v;
        mx = fmaxf(mx, v);
    }
    if (h == 1) { s_sum[c] = sum; s_max[c] = mx; }
    __syncthreads();
    if (h == 0) {
        sum += s_sum[c];
        mx = fmaxf(mx, s_max[c]);
        float cnt = (float)(e - s);
        g_Hg[g * D3 + c]            = sum / fmaxf(cnt, 1.f);
        g_Hg[g * D3 + DOUT + c]     = sum;
        g_Hg[g * D3 + 2 * DOUT + c] = mx;
    }
}

// bn2 + fc1 + fc2 + fc3 + log_softmax + scratch re-zero (16 blocks x 384)
__global__ void k_funnel(const float* __restrict__ g2, const float* __restrict__ be2,
                         const float* __restrict__ w1, const float* __restrict__ b1,
                         const float* __restrict__ w2, const float* __restrict__ b2,
                         const float* __restrict__ w3, const float* __restrict__ b3,
                         float* __restrict__ out) {
    __shared__ float smu[D3], srs[D3];
    __shared__ float sx[4][D3];
    __shared__ float a1s[4][H1DIM];
    __shared__ float a2s[4][H2DIM];
    int tid = threadIdx.x;                      // 384
    int r0 = blockIdx.x * 4;

    for (int c = tid; c < D3; c += 384) {
        float s = 0.f, ss = 0.f;
        for (int r = 0; r < G_GRAPHS; ++r) {
            float v = g_Hg[r * D3 + c];
            s += v; ss += v * v;
        }
        float mu = s * (1.0f / G_GRAPHS);
        float var = ss * (1.0f / G_GRAPHS) - mu * mu;
        smu[c] = mu;
        srs[c] = rsqrtf(var + BN_EPS);
    }
    __syncthreads();
    for (int e = tid; e < 4 * D3; e += 384) {
        int r = e / D3, c = e % D3;
        sx[r][c] = g2[c] * (g_Hg[(r0 + r) * D3 + c] - smu[c]) * srs[c] + be2[c];
    }
    __syncthreads();
    {
        int o = tid;
        float a0 = b1[o], a1 = a0, a2 = a0, a3 = a0;
        const float4* wr = (const float4*)&w1[o * D3];
#pragma unroll 4
        for (int k4 = 0; k4 < D3 / 4; ++k4) {
            float4 w = wr[k4];
            int k = k4 * 4;
            a0 += w.x * sx[0][k] + w.y * sx[0][k + 1] + w.z * sx[0][k + 2] + w.w * sx[0][k + 3];
            a1 += w.x * sx[1][k] + w.y * sx[1][k + 1] + w.z * sx[1][k + 2] + w.w * sx[1][k + 3];
            a2 += w.x * sx[2][k] + w.y * sx[2][k + 1] + w.z * sx[2][k + 2] + w.w * sx[2][k + 3];
            a3 += w.x * sx[3][k] + w.y * sx[3][k + 1] + w.z * sx[3][k + 2] + w.w * sx[3][k + 3];
        }
        a1s[0][o] = fmaxf(a0, 0.f);
        a1s[1][o] = fmaxf(a1, 0.f);
        a1s[2][o] = fmaxf(a2, 0.f);
        a1s[3][o] = fmaxf(a3, 0.f);
    }
    __syncthreads();
    if (tid < H2DIM) {
        int o = tid;
        float a0 = b2[o], a1 = a0, a2 = a0, a3 = a0;
        const float4* wr = (const float4*)&w2[o * H1DIM];
#pragma unroll 4
        for (int k4 = 0; k4 < H1DIM / 4; ++k4) {
            float4 w = wr[k4];
            int k = k4 * 4;
            a0 += w.x * a1s[0][k] + w.y * a1s[0][k + 1] + w.z * a1s[0][k + 2] + w.w * a1s[0][k + 3];
            a1 += w.x * a1s[1][k] + w.y * a1s[1][k + 1] + w.z * a1s[1][k + 2] + w.w * a1s[1][k + 3];
            a2 += w.x * a1s[2][k] + w.y * a1s[2][k + 1] + w.z * a1s[2][k + 2] + w.w * a1s[2][k + 3];
            a3 += w.x * a1s[3][k] + w.y * a1s[3][k + 1] + w.z * a1s[3][k + 2] + w.w * a1s[3][k + 3];
        }
        a2s[0][o] = fmaxf(a0, 0.f);
        a2s[1][o] = fmaxf(a1, 0.f);
        a2s[2][o] = fmaxf(a2, 0.f);
        a2s[3][o] = fmaxf(a3, 0.f);
    }
    __syncthreads();
    if (tid < 128) {
        int wrp = tid >> 5, lane = tid & 31;
        float z = -CUDART_INF_F;
        if (lane < NCLS) {
            z = b3[lane];
            const float* wr = &w3[lane * H2DIM];
            for (int k = 0; k < H2DIM; ++k) z = fmaf(wr[k], a2s[wrp][k], z);
        }
        float mx = z;
#pragma unroll
        for (int off = 16; off; off >>= 1) mx = fmaxf(mx, __shfl_xor_sync(0xffffffff, mx, off));
        float ex = (lane < NCLS) ? expf(z - mx) : 0.f;
        float sm = ex;
#pragma unroll
        for (int off = 16; off; off >>= 1) sm += __shfl_xor_sync(0xffffffff, sm, off);
        if (lane < NCLS) out[(r0 + wrp) * NCLS + lane] = z - mx - logf(sm);
    }
    int gidx = blockIdx.x * 384 + tid;
    for (int i = gidx; i < N_NODES; i += 16 * 384) {
        g_deg[i] = 0.f;
        g_rowCnt[i] = 0;
    }
    if (gidx < DOUT) { g_sum[gidx] = 0.f; g_sumsq[gidx] = 0.f; }
}

// ---------------- launch ----------------
extern "C" void kernel_launch(void* const* d_in, const int* in_sizes, int n_in,
                              void* d_out, int out_size) {
    const float* x     = (const float*)d_in[0];
    const int*   ei    = (const int*)d_in[1];
    const int*   batch = (const int*)d_in[2];
    const float* Wo    = (const float*)d_in[3];
    const float* b     = (const float*)d_in[4];
    const float* u     = (const float*)d_in[5];
    const float* bn1g  = (const float*)d_in[6];
    const float* bn1b  = (const float*)d_in[7];
    const float* bn2g  = (const float*)d_in[8];
    const float* bn2b  = (const float*)d_in[9];
    const float* w1    = (const float*)d_in[10];
    const float* b1    = (const float*)d_in[11];
    const float* w2    = (const float*)d_in[12];
    const float* b2    = (const float*)d_in[13];
    const float* w3    = (const float*)d_in[14];
    const float* b3    = (const float*)d_in[15];
    float*       out   = (float*)d_out;

    k_degree<<<N_EDGES / 256, 256>>>(ei);
    k_scan<<<1, 1024>>>(Wo, u);
    k_build<<<N_EDGES / 256, 256>>>(ei);
    k_spmm1<<<N_NODES * 32 / 256, 256>>>(x);
    k_spmm2<<<N_NODES * 32 / 256, 256>>>();
    k_gemm<<<dim3(N_NODES / 64, DOUT / 64), 256>>>(Wo, b);
    k_pool<<<G_GRAPHS, 384>>>(batch, bn1g, bn1b);
    k_funnel<<<16, 384>>>(bn2g, bn2b, w1, b1, w2, b2, w3, b3, out);
}